// round 17
// baseline (speedup 1.0000x reference)
#include <cuda_runtime.h>
#include <cuda_fp16.h>
#include <math.h>
#include <cstdint>

#define NTOK 4096      // T*B
#define DDIM 1024
#define HDIM 2048
#define ODIM 1024
#define NEXP 8
#define EMAX 4096      // max tokens per expert

// B panels in native [E][Kd][Nd] fp16 layout; GEMM loads B via ldmatrix.trans.
// A2 [E][EMAX][HDIM] fp16. GEMM1 gathers A rows from g_xnh via g_slots.

// ---------------- scratch (device globals; no allocation allowed) ----------
__device__ __half g_xnh[(size_t)NTOK * DDIM];                        // 8 MB fp16 LN output
__device__ int   g_cnt[NEXP];
__device__ int   g_slots[NEXP * NTOK];
__device__ float g_prob[2 * NTOK];
__device__ __half g_A2[(size_t)NEXP * EMAX * HDIM];                  // 134 MB
__device__ __half g_B1[(size_t)NEXP * DDIM * HDIM];                  // 33.5 MB [K][N]
__device__ __half g_B2[(size_t)NEXP * HDIM * ODIM];                  // 33.5 MB [K][N]

// ---------------- PTX helpers ----------------------------------------------
__device__ __forceinline__ uint32_t smem_to_u32(const void* p) {
    uint32_t a;
    asm("{ .reg .u64 t; cvta.to.shared.u64 t, %1; cvt.u32.u64 %0, t; }" : "=r"(a) : "l"(p));
    return a;
}
#define CP_ASYNC16(saddr, gptr) \
    asm volatile("cp.async.cg.shared.global [%0], [%1], 16;" :: "r"(saddr), "l"(gptr))
#define CP_COMMIT() asm volatile("cp.async.commit_group;" ::: "memory")
#define CP_WAIT1()  asm volatile("cp.async.wait_group 1;" ::: "memory")
#define LDSM_X4(R, addr) \
    asm volatile("ldmatrix.sync.aligned.m8n8.x4.shared.b16 {%0,%1,%2,%3}, [%4];" \
                 : "=r"((R)[0]), "=r"((R)[1]), "=r"((R)[2]), "=r"((R)[3]) : "r"(addr))
#define LDSM_X4_T(R, addr) \
    asm volatile("ldmatrix.sync.aligned.m8n8.x4.trans.shared.b16 {%0,%1,%2,%3}, [%4];" \
                 : "=r"((R)[0]), "=r"((R)[1]), "=r"((R)[2]), "=r"((R)[3]) : "r"(addr))
#define MMAH16816(D, A, B0, B1) \
    asm volatile("mma.sync.aligned.m16n8k16.row.col.f32.f16.f16.f32 " \
        "{%0,%1,%2,%3}, {%4,%5,%6,%7}, {%8,%9}, {%0,%1,%2,%3};" \
        : "+f"((D)[0]), "+f"((D)[1]), "+f"((D)[2]), "+f"((D)[3]) \
        : "r"((A)[0]), "r"((A)[1]), "r"((A)[2]), "r"((A)[3]), "r"(B0), "r"(B1))

__device__ __forceinline__ float gelu_exact(float v) {
    return 0.5f * v * (1.0f + erff(v * 0.70710678118654752440f));
}
__device__ __forceinline__ uint32_t pack_h2(float a, float b) {
    __half2 h = __floats2half2_rn(a, b);
    return *(uint32_t*)&h;
}

// ---------------- kernel 0: zero output + counters -------------------------
// Must run (complete) before prep_kernel: g_cnt feeds prep's atomics.
__global__ __launch_bounds__(256)
void zero_out_kernel(float* __restrict__ out) {
    if (blockIdx.x == 0 && threadIdx.x < NEXP) g_cnt[threadIdx.x] = 0;
    ((float4*)out)[(size_t)blockIdx.x * 256 + threadIdx.x] =
        make_float4(0.f, 0.f, 0.f, 0.f);
}

// ---------------- kernel 1: fused prep (LN/router + both weight converts) --
// blockIdx.x ranges:
//   [0, 512)           : LN + router + top2 (warp-per-token, 8 tokens/block)
//   [512, 8704)        : wconv1 (w1 fp32 -> g_B1 fp16 stream)
//   [8704, 16896)      : wconv2 (w2 fp32 -> g_B2 fp16 stream)
__global__ __launch_bounds__(256)
void prep_kernel(const float* __restrict__ x,
                 const float* __restrict__ gamma,
                 const float* __restrict__ beta,
                 const float* __restrict__ rw,
                 const float* __restrict__ w1,
                 const float* __restrict__ w2,
                 float* __restrict__ logits_out,
                 int write_logits)
{
    const int b = blockIdx.x;
    if (b >= 512) {
        // streaming fp32 -> fp16 weight conversion
        const float* src; __half* dst;
        size_t off;
        if (b < 8704) { src = w1; dst = g_B1; off = ((size_t)(b - 512) * 256 + threadIdx.x) * 8; }
        else          { src = w2; dst = g_B2; off = ((size_t)(b - 8704) * 256 + threadIdx.x) * 8; }
        float4 a = *(const float4*)(src + off);
        float4 c = *(const float4*)(src + off + 4);
        uint4 pk;
        pk.x = pack_h2(a.x, a.y); pk.y = pack_h2(a.z, a.w);
        pk.z = pack_h2(c.x, c.y); pk.w = pack_h2(c.z, c.w);
        *(uint4*)(dst + off) = pk;
        return;
    }

    // ---- LN + router (warp-per-token) ----
    const int warp = threadIdx.x >> 5, lane = threadIdx.x & 31;
    const int n = b * 8 + warp;
    const float4* xr = (const float4*)(x + (size_t)n * DDIM);
    float4 v[8];
    float s = 0.f;
    #pragma unroll
    for (int i = 0; i < 8; i++) {
        v[i] = xr[i * 32 + lane];
        s += (v[i].x + v[i].y) + (v[i].z + v[i].w);
    }
    #pragma unroll
    for (int o = 16; o; o >>= 1) s += __shfl_xor_sync(0xffffffffu, s, o);
    const float mu = s * (1.f / DDIM);
    float s2 = 0.f;
    #pragma unroll
    for (int i = 0; i < 8; i++) {
        float a = v[i].x - mu, bb = v[i].y - mu, c = v[i].z - mu, d = v[i].w - mu;
        s2 += (a * a + bb * bb) + (c * c + d * d);
    }
    #pragma unroll
    for (int o = 16; o; o >>= 1) s2 += __shfl_xor_sync(0xffffffffu, s2, o);
    const float rstd = rsqrtf(s2 * (1.f / DDIM) + 1e-5f);

    #pragma unroll
    for (int i = 0; i < 8; i++) {
        float4 g4 = ((const float4*)gamma)[i * 32 + lane];
        float4 b4 = ((const float4*)beta)[i * 32 + lane];
        v[i].x = (v[i].x - mu) * rstd * g4.x + b4.x;
        v[i].y = (v[i].y - mu) * rstd * g4.y + b4.y;
        v[i].z = (v[i].z - mu) * rstd * g4.z + b4.z;
        v[i].w = (v[i].w - mu) * rstd * g4.w + b4.w;
        uint2 hp = make_uint2(pack_h2(v[i].x, v[i].y), pack_h2(v[i].z, v[i].w));
        *(uint2*)&g_xnh[(size_t)n * DDIM + (i * 32 + lane) * 4] = hp;
    }

    float dp[NEXP];
    #pragma unroll
    for (int e = 0; e < NEXP; e++) {
        const float4* r4 = (const float4*)(rw + (size_t)e * DDIM);
        float d = 0.f;
        #pragma unroll
        for (int i = 0; i < 8; i++) {
            float4 r = r4[i * 32 + lane];
            d += (v[i].x * r.x + v[i].y * r.y) + (v[i].z * r.z + v[i].w * r.w);
        }
        #pragma unroll
        for (int o = 16; o; o >>= 1) d += __shfl_xor_sync(0xffffffffu, d, o);
        dp[e] = d;
    }

    if (lane == 0) {
        if (write_logits) {
            #pragma unroll
            for (int e = 0; e < NEXP; e++) logits_out[(size_t)n * NEXP + e] = dp[e];
        }
        int i0 = 0;
        #pragma unroll
        for (int e = 1; e < NEXP; e++) if (dp[e] > dp[i0]) i0 = e;
        int i1 = (i0 == 0) ? 1 : 0;
        #pragma unroll
        for (int e = 0; e < NEXP; e++) if (e != i0 && dp[e] > dp[i1]) i1 = e;
        float q = expf(dp[i1] - dp[i0]);
        float inv = 1.0f / (1.0f + q);
        g_prob[2 * n]     = inv;
        g_prob[2 * n + 1] = q * inv;
        int p0 = atomicAdd(&g_cnt[i0], 1); g_slots[i0 * NTOK + p0] = 2 * n;
        int p1 = atomicAdd(&g_cnt[i1], 1); g_slots[i1 * NTOK + p1] = 2 * n + 1;
    }
}

// ---------------- kernels 2/3: grouped fp16 GEMM via mma.sync --------------
// CTA tile 128x128, 8 warps (4x2), warp tile 32x64. K-chunk 64; 3-stage
// cp.async. A gathered (L1) / contiguous (L2); B in [K][N] layout loaded
// with ldmatrix.trans. L2 epilogue atomic-adds weighted GELU into d_out.
template<int LAYER>
__global__ __launch_bounds__(256, 2)
void mma_gemm(const float* __restrict__ bias_all,
              const float* __restrict__ mask,
              float* __restrict__ outp)
{
    constexpr int Kd = (LAYER == 1) ? DDIM : HDIM;
    constexpr int Nd = (LAYER == 1) ? HDIM : ODIM;
    constexpr int NCH = Kd / 64;
    constexpr int STAGE_BYTES = 32768;   // A 16K + B 16K
    const __half* __restrict__ Ball = (LAYER == 1) ? g_B1 : g_B2;

    const int e = blockIdx.z;
    const int cnt = g_cnt[e];
    const int m0 = blockIdx.x * 128;
    if (m0 >= cnt) return;
    const int n0 = blockIdx.y * 128;

    extern __shared__ __align__(1024) char smem[];
    const uint32_t smem_u = smem_to_u32(smem);
    __shared__ const __half* sArow[128];

    const int tid = threadIdx.x;
    const int lane = tid & 31;
    const int wid = tid >> 5;
    const int wm = wid >> 1;
    const int wn = wid & 1;

    if (tid < 128) {
        int r = m0 + tid;
        if (LAYER == 1) {
            int slot = (r < cnt) ? g_slots[e * NTOK + r] : g_slots[e * NTOK];
            sArow[tid] = g_xnh + (size_t)(slot >> 1) * DDIM;
        } else {
            sArow[tid] = g_A2 + ((size_t)e * EMAX + r) * HDIM;
        }
    }

    const __half* Bbase = Ball + (size_t)e * Kd * Nd + n0;

    const int lr = tid >> 3;          // A: 4 rows/thread, stride 32
    const int lch = tid & 7;          // 16B chunk in 128B A row
    const uint32_t lsw = (uint32_t)(lch * 16) ^ (uint32_t)((lr & 7) << 4);
    const int bkk = tid >> 4;         // B: 4 K-rows/thread, stride 16
    const int bg16 = tid & 15;        // 16B granule in 256B B row

    float acc[2][8][4];
    #pragma unroll
    for (int i = 0; i < 2; i++)
        #pragma unroll
        for (int j = 0; j < 8; j++)
            #pragma unroll
            for (int q = 0; q < 4; q++) acc[i][j][q] = 0.f;

    __syncthreads();   // sArow visible before first load

    auto load_stage = [&](int c, int st) {
        const int col = c * 64;       // element (A) / K-row (B) offset of chunk
        const uint32_t sA = smem_u + st * STAGE_BYTES;
        const uint32_t sB = sA + 16384;
        #pragma unroll
        for (int l = 0; l < 4; l++) {
            int r = lr + l * 32;
            CP_ASYNC16(sA + (uint32_t)(r * 128) + lsw,
                       (const char*)(sArow[r] + col) + lch * 16);
        }
        #pragma unroll
        for (int l = 0; l < 4; l++) {
            int kk = bkk + l * 16;
            CP_ASYNC16(sB + (uint32_t)(kk * 256) +
                           (uint32_t)((bg16 * 16) ^ ((kk & 7) << 4)),
                       (const char*)(Bbase + (size_t)(col + kk) * Nd) + bg16 * 16);
        }
    };

    const int rowA0 = wm * 32 + (lane & 15);
    const int kbA = (lane >> 4) * 8;
    const int gq = lane >> 3, l7 = lane & 7;

    auto compute_stage = [&](int st) {
        const uint32_t sA = smem_u + st * STAGE_BYTES;
        const uint32_t sB = sA + 16384;
        #pragma unroll
        for (int ks = 0; ks < 4; ks++) {
            uint32_t af[2][4], bf[4][4];
            #pragma unroll
            for (int mf = 0; mf < 2; mf++) {
                int row = rowA0 + mf * 16;
                uint32_t koff = (uint32_t)((ks * 16 + kbA) * 2) ^ (uint32_t)((row & 7) << 4);
                LDSM_X4(af[mf], sA + (uint32_t)(row * 128) + koff);
            }
            #pragma unroll
            for (int ng = 0; ng < 4; ng++) {
                int krow = ks * 16 + ((gq & 1) << 3) + l7;
                int ncol = wn * 64 + ng * 16 + (gq >> 1) * 8;
                uint32_t addr = sB + (uint32_t)(krow * 256) +
                                (uint32_t)((ncol * 2) ^ ((krow & 7) << 4));
                LDSM_X4_T(bf[ng], addr);
            }
            #pragma unroll
            for (int ng = 0; ng < 4; ng++)
                #pragma unroll
                for (int mf = 0; mf < 2; mf++) {
                    MMAH16816(acc[mf][2 * ng],     af[mf], bf[ng][0], bf[ng][1]);
                    MMAH16816(acc[mf][2 * ng + 1], af[mf], bf[ng][2], bf[ng][3]);
                }
        }
    };

    load_stage(0, 0); CP_COMMIT();
    load_stage(1, 1); CP_COMMIT();
    for (int c = 0; c < NCH; c++) {
        CP_WAIT1();
        __syncthreads();
        if (c + 2 < NCH) load_stage(c + 2, (c + 2) % 3);
        CP_COMMIT();
        compute_stage(c % 3);
    }

    // ---------------- epilogue --------------------------------------------
    const float* bias = bias_all + (size_t)e * Nd;
    const int rbase = m0 + wm * 32 + (lane >> 2);
    const int cbase = n0 + wn * 64 + (lane & 3) * 2;

    #pragma unroll
    for (int mf = 0; mf < 2; mf++) {
        #pragma unroll
        for (int cp = 0; cp < 2; cp++) {
            int row = rbase + mf * 16 + cp * 8;
            if (row >= cnt) continue;
            if (LAYER == 1) {
                __half* orow = g_A2 + ((size_t)e * EMAX + row) * HDIM;
                #pragma unroll
                for (int nf = 0; nf < 8; nf++) {
                    int col = cbase + nf * 8;
                    float v0 = gelu_exact(acc[mf][nf][2 * cp]     + bias[col]);
                    float v1 = gelu_exact(acc[mf][nf][2 * cp + 1] + bias[col + 1]);
                    *(uint32_t*)&orow[col] = pack_h2(v0, v1);
                }
            } else {
                int slot = g_slots[e * NTOK + row];
                int token = slot >> 1;
                float p = g_prob[slot] * mask[token];
                float* orow = outp + (size_t)token * ODIM;
                #pragma unroll
                for (int nf = 0; nf < 8; nf++) {
                    int col = cbase + nf * 8;
                    float v0 = gelu_exact(acc[mf][nf][2 * cp]     + bias[col]);
                    float v1 = gelu_exact(acc[mf][nf][2 * cp + 1] + bias[col + 1]);
                    atomicAdd(&orow[col],     p * v0);
                    atomicAdd(&orow[col + 1], p * v1);
                }
            }
        }
    }
}

// ---------------- launch ----------------------------------------------------
extern "C" void kernel_launch(void* const* d_in, const int* in_sizes, int n_in,
                              void* d_out, int out_size)
{
    const float* x     = (const float*)d_in[0];
    const float* mask  = (const float*)d_in[1];
    const float* gamma = (const float*)d_in[2];
    const float* beta  = (const float*)d_in[3];
    const float* rw    = (const float*)d_in[4];
    const float* w1    = (const float*)d_in[5];
    const float* b1    = (const float*)d_in[6];
    const float* w2    = (const float*)d_in[7];
    const float* b2    = (const float*)d_in[8];
    float* out = (float*)d_out;

    const int TBO = NTOK * ODIM;
    const int write_logits = (out_size >= TBO + NTOK * NEXP) ? 1 : 0;
    const int DSMEM = 98304;   // 3 stages x (16K A + 16K B)

    static int attr_done = 0;
    if (!attr_done) {
        cudaFuncSetAttribute(mma_gemm<1>, cudaFuncAttributeMaxDynamicSharedMemorySize, DSMEM);
        cudaFuncSetAttribute(mma_gemm<2>, cudaFuncAttributeMaxDynamicSharedMemorySize, DSMEM);
        attr_done = 1;
    }

    zero_out_kernel<<<TBO / 1024, 256>>>(out);
    prep_kernel<<<16896, 256>>>(x, gamma, beta, rw, w1, w2, out + TBO, write_logits);
    mma_gemm<1><<<dim3(EMAX / 128, HDIM / 128, NEXP), 256, DSMEM>>>(b1, mask, nullptr);
    mma_gemm<2><<<dim3(EMAX / 128, ODIM / 128, NEXP), 256, DSMEM>>>(b2, mask, out);
}